// round 3
// baseline (speedup 1.0000x reference)
#include <cuda_runtime.h>
#include <math.h>

// Problem constants (static per the reference module)
#define BB      4
#define NPER    2000
#define NATOMS  (BB*NPER)
#define NN      11            // n1 = 0..10
#define N3      21            // n3 = -10..10
#define NQ      3             // m2 quads: {0..3},{4..7},{8..10}
#define NT      256           // 8 warps: warp-pair per m2 slot

#define KSQ_MAX_F   9.8696044010893586f   // fp32(pi^2), as JAX compares
#define TWOPI_F     6.2831854820251465f
#define INV_SELF    0.0634936359342410f   // 1/(sigma*(2*pi)^1.5)
#define NORM_F      90.0474f
#define EPS_F       1e-6f

typedef unsigned long long u64;

__device__ __forceinline__ u64 pk(float lo, float hi) {
    u64 r; asm("mov.b64 %0, {%1, %2};" : "=l"(r) : "f"(lo), "f"(hi)); return r;
}
__device__ __forceinline__ float2 upk(u64 v) {
    float lo, hi; asm("mov.b64 {%0, %1}, %2;" : "=f"(lo), "=f"(hi) : "l"(v));
    return make_float2(lo, hi);
}
__device__ __forceinline__ void fma2(u64& d, u64 a, u64 b) {
    asm("fma.rn.f32x2 %0, %1, %2, %0;" : "+l"(d) : "l"(a), "l"(b));
}
__device__ __forceinline__ u64 add2(u64 a, u64 b) {
    u64 d; asm("add.rn.f32x2 %0, %1, %2;" : "=l"(d) : "l"(a), "l"(b)); return d;
}

// ---------------- device scratch ----------------
__device__ float  g_cinv[BB][3][3];
__device__ float  g_vol[BB];
__device__ float  g_pot[BB];
__device__ float2 g_tabx[BB][NN][NPER];   // q * e^{i 2pi n s0}
__device__ float2 g_taby[BB][NN][NPER];
__device__ float2 g_tabz[BB][NN][NPER];

// ---------------- kernel 1: phase tables via complex recurrence ----------------
__global__ void k_tab(const float* __restrict__ q, const float* __restrict__ r,
                      const float* __restrict__ cell) {
    int idx = blockIdx.x * blockDim.x + threadIdx.x;
    if (idx >= NATOMS) return;
    int b = idx / NPER;
    int a = idx - b * NPER;

    const float* m = cell + b * 9;
    float m00=m[0], m01=m[1], m02=m[2];
    float m10=m[3], m11=m[4], m12=m[5];
    float m20=m[6], m21=m[7], m22=m[8];
    float c00 = m11*m22 - m12*m21;
    float c01 = m12*m20 - m10*m22;
    float c02 = m10*m21 - m11*m20;
    float det = m00*c00 + m01*c01 + m02*c02;
    float inv = 1.0f / det;
    float i00 = c00 * inv;
    float i01 = (m02*m21 - m01*m22) * inv;
    float i02 = (m01*m12 - m02*m11) * inv;
    float i10 = c01 * inv;
    float i11 = (m00*m22 - m02*m20) * inv;
    float i12 = (m02*m10 - m00*m12) * inv;
    float i20 = c02 * inv;
    float i21 = (m01*m20 - m00*m21) * inv;
    float i22 = (m00*m11 - m01*m10) * inv;

    if (a == 0) {
        g_cinv[b][0][0]=i00; g_cinv[b][0][1]=i01; g_cinv[b][0][2]=i02;
        g_cinv[b][1][0]=i10; g_cinv[b][1][1]=i11; g_cinv[b][1][2]=i12;
        g_cinv[b][2][0]=i20; g_cinv[b][2][1]=i21; g_cinv[b][2][2]=i22;
        g_vol[b] = det;
        g_pot[b] = 0.0f;
    }

    float r0 = r[3*idx+0], r1 = r[3*idx+1], r2 = r[3*idx+2];
    float qv = q[idx];
    float s0 = r0*i00 + r1*i10 + r2*i20;
    float s1 = r0*i01 + r1*i11 + r2*i21;
    float s2 = r0*i02 + r1*i12 + r2*i22;

    float f, ex_s, ex_c, ey_s, ey_c, ez_s, ez_c;
    f = s0 - rintf(s0); sincospif(2.0f * f, &ex_s, &ex_c);
    f = s1 - rintf(s1); sincospif(2.0f * f, &ey_s, &ey_c);
    f = s2 - rintf(s2); sincospif(2.0f * f, &ez_s, &ez_c);

    float Xr = qv, Xi = 0.0f;     // q folded into X
    float Yr = 1.0f, Yi = 0.0f;
    float Zr = 1.0f, Zi = 0.0f;
    #pragma unroll
    for (int n = 0; n < NN; n++) {
        g_tabx[b][n][a] = make_float2(Xr, Xi);
        g_taby[b][n][a] = make_float2(Yr, Yi);
        g_tabz[b][n][a] = make_float2(Zr, Zi);
        float tXr = Xr*ex_c - Xi*ex_s;  Xi = Xr*ex_s + Xi*ex_c;  Xr = tXr;
        float tYr = Yr*ey_c - Yi*ey_s;  Yi = Yr*ey_s + Yi*ey_c;  Yr = tYr;
        float tZr = Zr*ez_c - Zi*ez_s;  Zi = Zr*ez_s + Zi*ez_c;  Zr = tZr;
    }
}

// ---------------- kernel 2: structure factors (f32x2) + fused reduction -------
// Block = (b, n1, m2-quad). Warp pair (2s, 2s+1) handles m2 = quad*4 + s.
__global__ void __launch_bounds__(NT) k_main() {
    int blk  = blockIdx.x;
    int b    = blk / (NN * NQ);
    int rem  = blk - b * (NN * NQ);
    int n1   = rem / NQ;
    int quad = rem - n1 * NQ;

    int w    = threadIdx.x >> 5;
    int lane = threadIdx.x & 31;
    int slot = w >> 1;
    int half = w & 1;
    int m2i  = quad * 4 + slot;
    bool dup = (m2i > 10);
    int  m2  = dup ? 10 : m2i;

    float g00 = TWOPI_F * g_cinv[b][0][0], g01 = TWOPI_F * g_cinv[b][1][0], g02 = TWOPI_F * g_cinv[b][2][0];
    float g10 = TWOPI_F * g_cinv[b][0][1], g11 = TWOPI_F * g_cinv[b][1][1], g12 = TWOPI_F * g_cinv[b][2][1];
    float g20 = TWOPI_F * g_cinv[b][0][2], g21 = TWOPI_F * g_cinv[b][1][2], g22 = TWOPI_F * g_cinv[b][2][2];

    // per-warp activity test (conservative)
    bool any = false;
    if (!dup) {
        #pragma unroll
        for (int s = 0; s < 2; s++) {
            float fn2 = s ? -(float)m2 : (float)m2;
            #pragma unroll
            for (int t = 0; t < N3; t++) {
                float n3 = (float)(t - 10);
                float kv0 = n1*g00 + fn2*g01 + n3*g02;
                float kv1 = n1*g10 + fn2*g11 + n3*g12;
                float kv2 = n1*g20 + fn2*g21 + n3*g22;
                float ksq = kv0*kv0 + kv1*kv1 + kv2*kv2;
                any = any || (ksq > 0.0f && ksq <= KSQ_MAX_F * 1.001f);
            }
        }
    }

    const float2* __restrict__ tx = &g_tabx[b][n1][0];
    const float2* __restrict__ ty = &g_taby[b][m2][0];
    const float2* __restrict__ tz = &g_tabz[b][0][0];

    // accumulators: sign s of n2 x {center, +n3 (P), -n3 (M stored (re,-im))}
    float cr0 = 0.f, ci0 = 0.f, cr1 = 0.f, ci1 = 0.f;
    u64 P0[10], M0[10], P1[10], M1[10];
    #pragma unroll
    for (int m = 0; m < 10; m++) { P0[m]=0; M0[m]=0; P1[m]=0; M1[m]=0; }

    if (any) {
        for (int a = half * 32 + lane; a < NPER; a += 64) {
            float2 X = tx[a];
            float2 Y = ty[a];
            float ar0 = X.x*Y.x - X.y*Y.y;   // n2 = +m2
            float ai0 = X.x*Y.y + X.y*Y.x;
            float ar1 = X.x*Y.x + X.y*Y.y;   // n2 = -m2
            float ai1 = X.y*Y.x - X.x*Y.y;
            cr0 += ar0; ci0 += ai0; cr1 += ar1; ci1 += ai1;
            u64 A0 = pk(ar0, ar0), I0 = pk(ai0, ai0), N0g = pk(-ai0, -ai0);
            u64 A1 = pk(ar1, ar1), I1 = pk(ai1, ai1), N1g = pk(-ai1, -ai1);
            #pragma unroll
            for (int m = 1; m <= 10; m++) {
                float2 Z = tz[m * NPER + a];
                float nzy = -Z.y;
                u64 w1 = pk(Z.x, Z.y);
                u64 w2 = pk(nzy, Z.x);
                // P (+n3): (re,im) += ar*(Zx,Zy) + ai*(-Zy,Zx)
                fma2(P0[m-1], A0, w1); fma2(P0[m-1], I0, w2);
                fma2(P1[m-1], A1, w1); fma2(P1[m-1], I1, w2);
                // M (-n3): (re,-im) += ar*(Zx,Zy) + (-ai)*(-Zy,Zx)
                fma2(M0[m-1], A0, w1); fma2(M0[m-1], N0g, w2);
                fma2(M1[m-1], A1, w1); fma2(M1[m-1], N1g, w2);
            }
        }
    }

    // ---- warp reduction (u64 shuffles + f32x2 adds) ----
    __shared__ float red[8][84];
    u64 packed[42];
    packed[0] = pk(cr0, ci0);
    packed[1] = pk(cr1, ci1);
    #pragma unroll
    for (int m = 0; m < 10; m++) {
        packed[2 + m]      = P0[m];
        packed[12 + m]     = M0[m];
        packed[22 + m]     = P1[m];
        packed[32 + m]     = M1[m];
    }
    #pragma unroll
    for (int j = 0; j < 42; j++) {
        u64 v = packed[j];
        v = add2(v, __shfl_xor_sync(0xffffffffu, v, 16));
        v = add2(v, __shfl_xor_sync(0xffffffffu, v, 8));
        v = add2(v, __shfl_xor_sync(0xffffffffu, v, 4));
        v = add2(v, __shfl_xor_sync(0xffffffffu, v, 2));
        v = add2(v, __shfl_xor_sync(0xffffffffu, v, 1));
        if (lane == 0) {
            float2 f2 = upk(v);
            red[w][2*j]   = f2.x;
            red[w][2*j+1] = f2.y;
        }
    }
    __syncthreads();

    // ---- per-kpoint weighting + block sum ----
    __shared__ float cont[NT];
    float c = 0.0f;
    if (threadIdx.x < 168) {
        int s4  = threadIdx.x / 42;        // slot
        int idx = threadIdx.x - s4 * 42;
        int sgn = idx / 21;                // 0: +m2, 1: -m2
        int j   = idx - sgn * 21;          // n3 index 0..20
        int mm2i = quad * 4 + s4;
        if (mm2i <= 10 && !(mm2i == 0 && sgn == 1)) {
            int wa = 2 * s4, wb = 2 * s4 + 1;
            float Sr, Si;
            if (j == 10) {
                int o = sgn * 2;           // packed[0]=c0, packed[1]=c1
                Sr = red[wa][o]   + red[wb][o];
                Si = red[wa][o+1] + red[wb][o+1];
            } else if (j > 10) {
                int o = (2 + (sgn ? 20 : 0) + (j - 11)) * 2;   // P bank
                Sr = red[wa][o]   + red[wb][o];
                Si = red[wa][o+1] + red[wb][o+1];
            } else {
                int o = (12 + (sgn ? 20 : 0) + (9 - j)) * 2;   // M bank, (re,-im)
                Sr =  red[wa][o]   + red[wb][o];
                Si = -(red[wa][o+1] + red[wb][o+1]);
            }
            float fn2 = sgn ? -(float)mm2i : (float)mm2i;
            float n3  = (float)(j - 10);
            float kv0 = n1*g00 + fn2*g01 + n3*g02;
            float kv1 = n1*g10 + fn2*g11 + n3*g12;
            float kv2 = n1*g20 + fn2*g21 + n3*g22;
            float ksq = kv0*kv0 + kv1*kv1 + kv2*kv2;
            if (ksq > 0.0f && ksq <= KSQ_MAX_F) {
                float wgt  = (n1 > 0) ? 2.0f : 1.0f;
                float kfac = expf(-0.5f * ksq) / (ksq + EPS_F);
                c = wgt * kfac * (Sr*Sr + Si*Si);
            }
        }
    }
    cont[threadIdx.x] = c;
    __syncthreads();
    #pragma unroll
    for (int s = NT/2; s > 0; s >>= 1) {
        if (threadIdx.x < s) cont[threadIdx.x] += cont[threadIdx.x + s];
        __syncthreads();
    }
    if (threadIdx.x == 0) atomicAdd(&g_pot[b], cont[0]);
}

// Index sanity for P/M banks:
//   j=11..20 -> m = j-10 = 1..10 -> packed index 2 + (m-1) (sign0) / 22 + (m-1) (sign1)
//   (2 + (j-11)) matches. j=0..9 -> m = 10-j = 10..1 -> packed 12 + (m-1) = 12 + (9-j). OK.

// ---------------- kernel 3: self energy + final output ----------------
__global__ void k_final(const float* __restrict__ q, float* __restrict__ out) {
    int b = blockIdx.x;
    __shared__ float sd[128];
    float s = 0.0f;
    for (int a = threadIdx.x; a < NPER; a += 128) {
        float qv = q[b * NPER + a];
        s += qv * qv;
    }
    sd[threadIdx.x] = s;
    __syncthreads();
    #pragma unroll
    for (int t = 64; t > 0; t >>= 1) {
        if (threadIdx.x < t) sd[threadIdx.x] += sd[threadIdx.x + t];
        __syncthreads();
    }
    if (threadIdx.x == 0) {
        float pot = g_pot[b] / g_vol[b] - sd[0] * INV_SELF;
        out[b] = pot * NORM_F;
    }
}

// ---------------- launch ----------------
extern "C" void kernel_launch(void* const* d_in, const int* in_sizes, int n_in,
                              void* d_out, int out_size) {
    const float* q    = (const float*)d_in[0];
    const float* r    = (const float*)d_in[1];
    const float* cell = (const float*)d_in[2];
    float* out = (float*)d_out;

    k_tab<<<(NATOMS + 127) / 128, 128>>>(q, r, cell);
    k_main<<<BB * NN * NQ, NT>>>();
    k_final<<<BB, 128>>>(q, out);
}

// round 4
// speedup vs baseline: 1.5664x; 1.5664x over previous
#include <cuda_runtime.h>
#include <math.h>

// Problem constants (static per the reference module)
#define BB      4
#define NPER    2000
#define NATOMS  (BB*NPER)
#define NN      11            // n = 0..10 per axis
#define NT      128           // threads per k_main block

#define KSQ_MAX_F   9.8696044010893586f   // fp32(pi^2), as JAX compares
#define TWOPI_F     6.2831854820251465f
#define INV_SELF    0.0634936359342410f   // 1/(sigma*(2*pi)^1.5)
#define NORM_F      90.0474f
#define EPS_F       1e-6f

// ---------------- device scratch ----------------
__device__ float  g_cinv[BB][3][3];
__device__ float  g_vol[BB];
__device__ float  g_pot[BB];
__device__ float2 g_tabx[BB][NN][NPER];   // q * e^{i 2pi n s0}
__device__ float2 g_taby[BB][NN][NPER];   //     e^{i 2pi n s1}
// z-table transposed per atom: 12 float2 slots (96 B, 16B-aligned rows)
// n = 1..5 -> slot n-1 (0..4); n = 6..10 -> slot n (6..10); slots 5,11 unused
__device__ float4 g_tabz[BB][NPER][6];

// ---------------- kernel 1: phase tables, thread = (atom, n) ----------------
__global__ void k_tab(const float* __restrict__ q, const float* __restrict__ r,
                      const float* __restrict__ cell) {
    int idx = blockIdx.x * blockDim.x + threadIdx.x;
    if (idx >= NATOMS * NN) return;
    int n  = idx / NATOMS;
    int ga = idx - n * NATOMS;
    int b  = ga / NPER;
    int a  = ga - b * NPER;

    const float* m = cell + b * 9;
    float m00=m[0], m01=m[1], m02=m[2];
    float m10=m[3], m11=m[4], m12=m[5];
    float m20=m[6], m21=m[7], m22=m[8];
    float c00 = m11*m22 - m12*m21;
    float c01 = m12*m20 - m10*m22;
    float c02 = m10*m21 - m11*m20;
    float det = m00*c00 + m01*c01 + m02*c02;
    float inv = 1.0f / det;
    float i00 = c00 * inv;
    float i01 = (m02*m21 - m01*m22) * inv;
    float i02 = (m01*m12 - m02*m11) * inv;
    float i10 = c01 * inv;
    float i11 = (m00*m22 - m02*m20) * inv;
    float i12 = (m02*m10 - m00*m12) * inv;
    float i20 = c02 * inv;
    float i21 = (m01*m20 - m00*m21) * inv;
    float i22 = (m00*m11 - m01*m10) * inv;

    if (n == 0 && a == 0) {
        g_cinv[b][0][0]=i00; g_cinv[b][0][1]=i01; g_cinv[b][0][2]=i02;
        g_cinv[b][1][0]=i10; g_cinv[b][1][1]=i11; g_cinv[b][1][2]=i12;
        g_cinv[b][2][0]=i20; g_cinv[b][2][1]=i21; g_cinv[b][2][2]=i22;
        g_vol[b] = det;
        g_pot[b] = 0.0f;
    }

    float r0 = r[3*ga+0], r1 = r[3*ga+1], r2 = r[3*ga+2];
    float qv = q[ga];
    float s0 = r0*i00 + r1*i10 + r2*i20;
    float s1 = r0*i01 + r1*i11 + r2*i21;
    float s2 = r0*i02 + r1*i12 + r2*i22;

    float fn = (float)n;
    float u, f, sx, cx, sy, cy, sz, cz;
    u = fn * s0; f = u - rintf(u); sincospif(2.0f * f, &sx, &cx);
    u = fn * s1; f = u - rintf(u); sincospif(2.0f * f, &sy, &cy);
    u = fn * s2; f = u - rintf(u); sincospif(2.0f * f, &sz, &cz);

    g_tabx[b][n][a] = make_float2(qv * cx, qv * sx);
    g_taby[b][n][a] = make_float2(cy, sy);
    if (n >= 1) {
        int slot = (n <= 5) ? (n - 1) : n;
        ((float2*)&g_tabz[b][a][0])[slot] = make_float2(cz, sz);
    }
}

// ---------------- kernel 2 body: structure factors + fused reduction ----------
// Block = (b, n1, m2, S). S=0: n3 in [-5,5] (m=0..5); S=1: |n3| in [6,10].
// Both n2 signs handled in-block. Full atom range per block => complete S.
template<int S>
__device__ __forceinline__ void k_main_body() {
    int blk = blockIdx.x;
    int b   = blk / 121;
    int rem = blk - b * 121;
    int n1  = rem / 11;
    int m2  = rem - n1 * 11;

    constexpr int  MLO  = S ? 6 : 1;
    constexpr bool HASC = (S == 0);
    constexpr int  ENT  = HASC ? 11 : 10;   // n3 entries per sign
    constexpr int  ACCN = HASC ? 22 : 20;   // floats per sign
    constexpr int  CB   = HASC ? 2 : 0;     // P-bank offset

    float g00 = TWOPI_F*g_cinv[b][0][0], g01 = TWOPI_F*g_cinv[b][1][0], g02 = TWOPI_F*g_cinv[b][2][0];
    float g10 = TWOPI_F*g_cinv[b][0][1], g11 = TWOPI_F*g_cinv[b][1][1], g12 = TWOPI_F*g_cinv[b][2][1];
    float g20 = TWOPI_F*g_cinv[b][0][2], g21 = TWOPI_F*g_cinv[b][1][2], g22 = TWOPI_F*g_cinv[b][2][2];

    // conservative per-block activity filter over this block's n3 set
    bool any = false;
    #pragma unroll
    for (int sg = 0; sg < 2; sg++) {
        float fn2 = sg ? -(float)m2 : (float)m2;
        #pragma unroll
        for (int j = 0; j < ENT; j++) {
            int n3i = S ? ((j < 5) ? j - 10 : j + 1) : (j - 5);
            float n3 = (float)n3i;
            float kv0 = n1*g00 + fn2*g01 + n3*g02;
            float kv1 = n1*g10 + fn2*g11 + n3*g12;
            float kv2 = n1*g20 + fn2*g21 + n3*g22;
            float ksq = kv0*kv0 + kv1*kv1 + kv2*kv2;
            any = any || (ksq > 0.0f && ksq <= KSQ_MAX_F * 1.001f);
        }
    }
    if (!any) return;

    const float2* __restrict__ tx = &g_tabx[b][n1][0];
    const float2* __restrict__ ty = &g_taby[b][m2][0];

    // per-sign layout: [center re,im (if HASC)] [P m=MLO..MLO+4 re,im] [M ...]
    float acc[2*ACCN];
    #pragma unroll
    for (int j = 0; j < 2*ACCN; j++) acc[j] = 0.0f;

    for (int a = threadIdx.x; a < NPER; a += NT) {
        float2 X = tx[a];
        float2 Y = ty[a];
        float ar0 = X.x*Y.x - X.y*Y.y;   // n2 = +m2
        float ai0 = X.x*Y.y + X.y*Y.x;
        float ar1 = X.x*Y.x + X.y*Y.y;   // n2 = -m2
        float ai1 = X.y*Y.x - X.x*Y.y;
        float nar0 = -ar0, nai0 = -ai0, nar1 = -ar1, nai1 = -ai1;
        if (HASC) {
            acc[0]      += ar0; acc[1]      += ai0;
            acc[ACCN+0] += ar1; acc[ACCN+1] += ai1;
        }
        const float4* zr = &g_tabz[b][a][0];
        float4 za = zr[S ? 3 : 0];
        float4 zb = zr[S ? 4 : 1];
        float2 zc = ((const float2*)zr)[S ? 10 : 4];
        float zx[5] = {za.x, za.z, zb.x, zb.z, zc.x};
        float zy[5] = {za.y, za.w, zb.y, zb.w, zc.y};
        #pragma unroll
        for (int mi = 0; mi < 5; mi++) {
            float Zx = zx[mi], Zy = zy[mi];
            // sign 0: P(+n3) and M(-n3)
            acc[CB+2*mi]           = fmaf(ar0, Zx, fmaf(nai0, Zy, acc[CB+2*mi]));
            acc[CB+2*mi+1]         = fmaf(ar0, Zy, fmaf(ai0,  Zx, acc[CB+2*mi+1]));
            acc[CB+10+2*mi]        = fmaf(ar0, Zx, fmaf(ai0,  Zy, acc[CB+10+2*mi]));
            acc[CB+10+2*mi+1]      = fmaf(nar0,Zy, fmaf(ai0,  Zx, acc[CB+10+2*mi+1]));
            // sign 1
            acc[ACCN+CB+2*mi]      = fmaf(ar1, Zx, fmaf(nai1, Zy, acc[ACCN+CB+2*mi]));
            acc[ACCN+CB+2*mi+1]    = fmaf(ar1, Zy, fmaf(ai1,  Zx, acc[ACCN+CB+2*mi+1]));
            acc[ACCN+CB+10+2*mi]   = fmaf(ar1, Zx, fmaf(ai1,  Zy, acc[ACCN+CB+10+2*mi]));
            acc[ACCN+CB+10+2*mi+1] = fmaf(nar1,Zy, fmaf(ai1,  Zx, acc[ACCN+CB+10+2*mi+1]));
        }
    }

    // ---- 3-level warp reduce -> 16 partials per entry in smem ----
    __shared__ float red[16][44];
    __shared__ float cont[NT];
    int w = threadIdx.x >> 5, lane = threadIdx.x & 31;
    #pragma unroll
    for (int j = 0; j < 2*ACCN; j++) {
        float v = acc[j];
        v += __shfl_xor_sync(0xffffffffu, v, 16);
        v += __shfl_xor_sync(0xffffffffu, v, 8);
        v += __shfl_xor_sync(0xffffffffu, v, 4);
        if (lane < 4) red[w*4 + lane][j] = v;
    }
    __syncthreads();

    // ---- per-kpoint weighting ----
    float c = 0.0f;
    int t = threadIdx.x;
    if (t < 2*ENT) {
        int sgn = t / ENT, j = t - sgn*ENT;
        if (!(m2 == 0 && sgn == 1)) {          // n2 = -0 is a duplicate
            int n3i = S ? ((j < 5) ? j - 10 : j + 1) : (j - 5);
            int base;
            if (HASC && n3i == 0) {
                base = 0;
            } else {
                int mm = n3i < 0 ? -n3i : n3i;
                int mi = mm - MLO;
                base = CB + ((n3i > 0) ? 0 : 10) + 2*mi;
            }
            float Sr = 0.0f, Si = 0.0f;
            #pragma unroll
            for (int p = 0; p < 16; p++) {
                Sr += red[p][sgn*ACCN + base];
                Si += red[p][sgn*ACCN + base + 1];
            }
            float fn2 = sgn ? -(float)m2 : (float)m2;
            float n3  = (float)n3i;
            float kv0 = n1*g00 + fn2*g01 + n3*g02;
            float kv1 = n1*g10 + fn2*g11 + n3*g12;
            float kv2 = n1*g20 + fn2*g21 + n3*g22;
            float ksq = kv0*kv0 + kv1*kv1 + kv2*kv2;
            if (ksq > 0.0f && ksq <= KSQ_MAX_F) {
                float wgt  = (n1 > 0) ? 2.0f : 1.0f;
                float kfac = expf(-0.5f * ksq) / (ksq + EPS_F);
                c = wgt * kfac * (Sr*Sr + Si*Si);
            }
        }
    }
    cont[t] = c;
    __syncthreads();
    #pragma unroll
    for (int s = NT/2; s > 0; s >>= 1) {
        if (t < s) cont[t] += cont[t + s];
        __syncthreads();
    }
    if (t == 0) atomicAdd(&g_pot[b], cont[0]);
}

__global__ void __launch_bounds__(NT) k_main() {
    if (blockIdx.y == 0) k_main_body<0>();
    else                 k_main_body<1>();
}

// ---------------- kernel 3: self energy + final output ----------------
__global__ void k_final(const float* __restrict__ q, float* __restrict__ out) {
    int b = blockIdx.x;
    __shared__ float sd[128];
    float s = 0.0f;
    for (int a = threadIdx.x; a < NPER; a += 128) {
        float qv = q[b * NPER + a];
        s += qv * qv;
    }
    sd[threadIdx.x] = s;
    __syncthreads();
    #pragma unroll
    for (int t = 64; t > 0; t >>= 1) {
        if (threadIdx.x < t) sd[threadIdx.x] += sd[threadIdx.x + t];
        __syncthreads();
    }
    if (threadIdx.x == 0) {
        float pot = g_pot[b] / g_vol[b] - sd[0] * INV_SELF;
        out[b] = pot * NORM_F;
    }
}

// ---------------- launch ----------------
extern "C" void kernel_launch(void* const* d_in, const int* in_sizes, int n_in,
                              void* d_out, int out_size) {
    const float* q    = (const float*)d_in[0];
    const float* r    = (const float*)d_in[1];
    const float* cell = (const float*)d_in[2];
    float* out = (float*)d_out;

    k_tab<<<(NATOMS * NN + 127) / 128, 128>>>(q, r, cell);
    k_main<<<dim3(BB * 121, 2), NT>>>();
    k_final<<<BB, 128>>>(q, out);
}